// round 6
// baseline (speedup 1.0000x reference)
#include <cuda_runtime.h>
#include <math.h>

#define BB 16
#define CC 256
#define HH 64
#define WW 64
#define KK 4
#define OO 256
#define HID 65
#define TEMP 34.0f

typedef unsigned long long ull;

// scratch
__device__ float g_pooled[BB*CC];
__device__ float g_att[BB*KK];
__device__ float g_aggw[BB*OO*CC*9];   // ~37.7 MB

// ---------------------------------------------------------------------------
// packed fp32 helpers (Blackwell FFMA2 via PTX fma.rn.f32x2)
// ---------------------------------------------------------------------------
__device__ __forceinline__ ull ffma2(ull a, ull b, ull c) {
    ull d;
    asm("fma.rn.f32x2 %0, %1, %2, %3;" : "=l"(d) : "l"(a), "l"(b), "l"(c));
    return d;
}
__device__ __forceinline__ ull pk(float lo, float hi) {
    ull d;
    asm("mov.b64 %0, {%1, %2};" : "=l"(d) : "f"(lo), "f"(hi));
    return d;
}
__device__ __forceinline__ void upk(ull v, float& lo, float& hi) {
    asm("mov.b64 {%0, %1}, %2;" : "=f"(lo), "=f"(hi) : "l"(v));
}

// ---------------------------------------------------------------------------
// Kernel 1: global average pool  -> g_pooled[b*C + c]
// ---------------------------------------------------------------------------
__global__ void pool_kernel(const float* __restrict__ x) {
    int bc = blockIdx.x;
    const float4* p = (const float4*)(x + (size_t)bc * (HH*WW));
    float s = 0.f;
    for (int i = threadIdx.x; i < HH*WW/4; i += blockDim.x) {
        float4 v = p[i];
        s += (v.x + v.y) + (v.z + v.w);
    }
    __shared__ float red[128];
    red[threadIdx.x] = s;
    __syncthreads();
    for (int off = 64; off > 0; off >>= 1) {
        if (threadIdx.x < off) red[threadIdx.x] += red[threadIdx.x + off];
        __syncthreads();
    }
    if (threadIdx.x == 0) g_pooled[bc] = red[0] * (1.0f/(HH*WW));
}

// ---------------------------------------------------------------------------
// Kernel 2: MLP + softmax(logits/T)  -> g_att[b*K + k]
// ---------------------------------------------------------------------------
__global__ void att_kernel(const float* __restrict__ w_fc1,
                           const float* __restrict__ w_fc2,
                           const float* __restrict__ b_fc2) {
    __shared__ float pooled_s[BB*CC];
    __shared__ float h_s[BB][HID];
    __shared__ float logits_s[BB][KK];
    int tid = threadIdx.x;
    for (int i = tid; i < BB*CC; i += blockDim.x) pooled_s[i] = g_pooled[i];
    __syncthreads();
    for (int t = tid; t < BB*HID; t += blockDim.x) {
        int b = t / HID, j = t - b*HID;
        float acc = 0.f;
        const float* wr = w_fc1 + j*CC;
        const float* pr = pooled_s + b*CC;
        #pragma unroll 4
        for (int c = 0; c < CC; c++) acc += pr[c]*wr[c];
        h_s[b][j] = fmaxf(acc, 0.f);
    }
    __syncthreads();
    if (tid < BB*KK) {
        int b = tid / KK, k = tid - b*KK;
        float acc = b_fc2[k];
        const float* wr = w_fc2 + k*HID;
        for (int j = 0; j < HID; j++) acc += h_s[b][j]*wr[j];
        logits_s[b][k] = acc * (1.0f/TEMP);
    }
    __syncthreads();
    if (tid < BB) {
        int b = tid;
        float m = logits_s[b][0];
        #pragma unroll
        for (int k = 1; k < KK; k++) m = fmaxf(m, logits_s[b][k]);
        float e[KK]; float s = 0.f;
        #pragma unroll
        for (int k = 0; k < KK; k++) { e[k] = expf(logits_s[b][k] - m); s += e[k]; }
        float inv = 1.0f / s;
        #pragma unroll
        for (int k = 0; k < KK; k++) g_att[b*KK + k] = e[k] * inv;
    }
}

// ---------------------------------------------------------------------------
// Kernel 3: aggregate weights (float4-vectorized)
// ---------------------------------------------------------------------------
__global__ void aggw_kernel(const float* __restrict__ wt) {
    const int per4 = OO*CC*9/4;                // 147456
    int m = blockIdx.x*blockDim.x + threadIdx.x;
    if (m >= BB*per4) return;
    int b = m / per4;
    int r = m - b*per4;
    float a0 = g_att[b*4+0], a1 = g_att[b*4+1];
    float a2 = g_att[b*4+2], a3 = g_att[b*4+3];
    const float4* w4 = (const float4*)wt;
    float4 v0 = w4[r], v1 = w4[per4 + r], v2 = w4[2*per4 + r], v3 = w4[3*per4 + r];
    float4 o;
    o.x = a0*v0.x + a1*v1.x + a2*v2.x + a3*v3.x;
    o.y = a0*v0.y + a1*v1.y + a2*v2.y + a3*v3.y;
    o.z = a0*v0.z + a1*v1.z + a2*v2.z + a3*v3.z;
    o.w = a0*v0.w + a1*v1.w + a2*v2.w + a3*v3.w;
    ((float4*)g_aggw)[m] = o;
}

// ---------------------------------------------------------------------------
// Kernel 4: direct 3x3 conv with packed f32x2 FMA.
// Block: 64 O x (16x16) px, 256 threads. Thread: 8 O x 8 px (4 f32x2 pairs).
// C chunked by 8 through shared memory. Weights pair-duplicated in smem.
// ---------------------------------------------------------------------------
#define XS_STRIDE 20
#define XS_PLANE (18*XS_STRIDE)               // 360 floats per c
#define XS_FLOATS (8*XS_PLANE)                // 2880
#define WS_FLOATS (8*3*64*8)                  // 12288
#define CONV_SMEM_BYTES ((XS_FLOATS + WS_FLOATS)*4)   // 60672

__global__ __launch_bounds__(256, 2)
void conv_kernel(const float* __restrict__ x,
                 const float* __restrict__ bias,
                 float* __restrict__ out) {
    extern __shared__ float sm[];
    float* x_s = sm;                  // [8][18][20]
    float* w_s = sm + XS_FLOATS;      // [cc][r][o][8] = w0,w0,w1,w1,w2,w2,pad,pad

    const int tid  = threadIdx.x;
    const int b    = blockIdx.z;
    const int o0   = blockIdx.y * 64;
    const int t    = blockIdx.x;               // 0..15 -> 4x4 spatial tiles
    const int y0   = (t >> 2) * 16;
    const int x0   = (t & 3)  * 16;
    const int osub = (tid >> 5) * 8;           // 0,8,...,56
    const int pg   = tid & 31;
    const int rloc = pg >> 1;                  // 0..15 row within tile
    const int cb   = (pg & 1) * 8;             // 0 or 8 col base

    ull acc[8][4];
    #pragma unroll
    for (int oo = 0; oo < 8; oo++)
        #pragma unroll
        for (int p = 0; p < 4; p++) acc[oo][p] = 0ull;

    const float* xb = x + (size_t)(b*CC) * (HH*WW);
    const float* wb = g_aggw + (size_t)((b*OO + o0)*CC) * 9;

    for (int c0 = 0; c0 < CC; c0 += 8) {
        __syncthreads();
        // ---- load x tile (18x18 + zero halo), rows padded to 20 ----
        for (int e = tid; e < 8*324; e += 256) {
            int c   = e / 324;
            int rem = e - c*324;
            int yy  = rem / 18;
            int xx  = rem - yy*18;
            int gy  = y0 - 1 + yy;
            int gx  = x0 - 1 + xx;
            float v = 0.f;
            if ((unsigned)gy < 64u && (unsigned)gx < 64u)
                v = xb[(size_t)(c0 + c)*4096 + gy*64 + gx];
            x_s[c*XS_PLANE + yy*XS_STRIDE + xx] = v;
        }
        // ---- load weights, duplicate each tap into a f32x2 pair ----
        for (int idx = tid; idx < 1536; idx += 256) {
            int o   = idx / 24;
            int rem = idx - o*24;
            int cc  = rem / 3;
            int r   = rem - cc*3;
            const float* src = wb + (size_t)o*(CC*9) + (c0 + cc)*9 + r*3;
            float w0 = src[0], w1 = src[1], w2 = src[2];
            float* dst = w_s + (((cc*3 + r)*64) + o)*8;
            dst[0] = w0; dst[1] = w0;
            dst[2] = w1; dst[3] = w1;
            dst[4] = w2; dst[5] = w2;
        }
        __syncthreads();

        // ---- compute ----
        for (int cc = 0; cc < 8; cc++) {
            const float* xrow0 = x_s + cc*XS_PLANE + rloc*XS_STRIDE + cb;
            #pragma unroll
            for (int r = 0; r < 3; r++) {
                const float* xr = xrow0 + r*XS_STRIDE;
                float4 a4 = *(const float4*)(xr);
                float4 b4 = *(const float4*)(xr + 4);
                float2 c2 = *(const float2*)(xr + 8);
                ull E[5], O[4];
                E[0] = pk(a4.x, a4.y); E[1] = pk(a4.z, a4.w);
                E[2] = pk(b4.x, b4.y); E[3] = pk(b4.z, b4.w);
                E[4] = pk(c2.x, c2.y);
                O[0] = pk(a4.y, a4.z); O[1] = pk(a4.w, b4.x);
                O[2] = pk(b4.y, b4.z); O[3] = pk(b4.w, c2.x);
                const float* wbase = w_s + (((cc*3 + r)*64) + osub)*8;
                #pragma unroll
                for (int oo = 0; oo < 8; oo++) {
                    const ull* wp = (const ull*)(wbase + oo*8);
                    ull w00 = wp[0];      // (w0,w0)
                    ull w11 = wp[1];      // (w1,w1)
                    ull w22 = wp[2];      // (w2,w2)
                    #pragma unroll
                    for (int p = 0; p < 4; p++) {
                        acc[oo][p] = ffma2(w00, E[p],   acc[oo][p]);
                        acc[oo][p] = ffma2(w11, O[p],   acc[oo][p]);
                        acc[oo][p] = ffma2(w22, E[p+1], acc[oo][p]);
                    }
                }
            }
        }
    }

    // ---- epilogue: + agg_b, store float4 ----
    float a0 = g_att[b*4+0], a1 = g_att[b*4+1];
    float a2 = g_att[b*4+2], a3 = g_att[b*4+3];
    #pragma unroll
    for (int oo = 0; oo < 8; oo++) {
        int o = o0 + osub + oo;
        float ab = a0*bias[o] + a1*bias[OO + o] + a2*bias[2*OO + o] + a3*bias[3*OO + o];
        float v[8];
        #pragma unroll
        for (int p = 0; p < 4; p++) {
            float lo, hi;
            upk(acc[oo][p], lo, hi);
            v[2*p]   = lo + ab;
            v[2*p+1] = hi + ab;
        }
        float* op = out + (size_t)(b*OO + o)*4096 + (y0 + rloc)*64 + x0 + cb;
        *(float4*)(op)     = make_float4(v[0], v[1], v[2], v[3]);
        *(float4*)(op + 4) = make_float4(v[4], v[5], v[6], v[7]);
    }
}

// ---------------------------------------------------------------------------
extern "C" void kernel_launch(void* const* d_in, const int* in_sizes, int n_in,
                              void* d_out, int out_size) {
    const float* x     = (const float*)d_in[0];
    const float* w_fc1 = (const float*)d_in[1];
    const float* w_fc2 = (const float*)d_in[2];
    const float* b_fc2 = (const float*)d_in[3];
    const float* wt    = (const float*)d_in[4];
    const float* bias  = (const float*)d_in[5];
    float* out = (float*)d_out;

    cudaFuncSetAttribute(conv_kernel,
                         cudaFuncAttributeMaxDynamicSharedMemorySize,
                         CONV_SMEM_BYTES);

    pool_kernel<<<BB*CC, 128>>>(x);
    att_kernel<<<1, 1024>>>(w_fc1, w_fc2, b_fc2);
    aggw_kernel<<<(BB*OO*CC*9/4 + 255)/256, 256>>>(wt);
    conv_kernel<<<dim3(16, 4, 16), 256, CONV_SMEM_BYTES>>>(x, bias, out);
}

// round 9
// speedup vs baseline: 2.3647x; 2.3647x over previous
#include <cuda_runtime.h>
#include <cuda_bf16.h>
#include <math.h>
#include <stdint.h>

#define BB 16
#define CC 256
#define HH 64
#define WW 64
#define KK 4
#define OO 256
#define HID 65
#define TEMP 34.0f

// ---------------------------------------------------------------------------
// device scratch
// ---------------------------------------------------------------------------
__device__ float g_pooled[BB*CC];
__device__ float g_att[BB*KK];
__device__ __nv_bfloat16 g_awhi[(size_t)BB*9*OO*CC];   // [b][tap][o][c]
__device__ __nv_bfloat16 g_awlo[(size_t)BB*9*OO*CC];
__device__ __nv_bfloat16 g_xthi[(size_t)BB*HH*WW*CC];  // [b][pixel][c]
__device__ __nv_bfloat16 g_xtlo[(size_t)BB*HH*WW*CC];

// ---------------------------------------------------------------------------
// PTX helpers (all plain sm_80/sm_90 features -> work on .target sm_103)
// ---------------------------------------------------------------------------
__device__ __forceinline__ uint32_t smem_u32(const void* p) {
    uint32_t a;
    asm("{ .reg .u64 t; cvta.to.shared.u64 t, %1; cvt.u32.u64 %0, t; }"
        : "=r"(a) : "l"(p));
    return a;
}
__device__ __forceinline__ void cp16(uint32_t dst, const void* src, uint32_t sz) {
    asm volatile("cp.async.cg.shared.global [%0], [%1], 16, %2;"
                 :: "r"(dst), "l"(src), "r"(sz) : "memory");
}
__device__ __forceinline__ void ldsm4(uint32_t* r, uint32_t addr) {
    asm volatile("ldmatrix.sync.aligned.m8n8.x4.shared.b16 {%0,%1,%2,%3}, [%4];"
                 : "=r"(r[0]), "=r"(r[1]), "=r"(r[2]), "=r"(r[3]) : "r"(addr));
}
__device__ __forceinline__ void mma_bf16(float* d, const uint32_t* a,
                                         uint32_t b0, uint32_t b1) {
    asm volatile(
        "mma.sync.aligned.m16n8k16.row.col.f32.bf16.bf16.f32 "
        "{%0,%1,%2,%3}, {%4,%5,%6,%7}, {%8,%9}, {%0,%1,%2,%3};"
        : "+f"(d[0]), "+f"(d[1]), "+f"(d[2]), "+f"(d[3])
        : "r"(a[0]), "r"(a[1]), "r"(a[2]), "r"(a[3]), "r"(b0), "r"(b1));
}

// ---------------------------------------------------------------------------
// Kernel 1: global average pool
// ---------------------------------------------------------------------------
__global__ void pool_kernel(const float* __restrict__ x) {
    int bc = blockIdx.x;
    const float4* p = (const float4*)(x + (size_t)bc * (HH*WW));
    float s = 0.f;
    for (int i = threadIdx.x; i < HH*WW/4; i += blockDim.x) {
        float4 v = p[i];
        s += (v.x + v.y) + (v.z + v.w);
    }
    __shared__ float red[128];
    red[threadIdx.x] = s;
    __syncthreads();
    for (int off = 64; off > 0; off >>= 1) {
        if (threadIdx.x < off) red[threadIdx.x] += red[threadIdx.x + off];
        __syncthreads();
    }
    if (threadIdx.x == 0) g_pooled[bc] = red[0] * (1.0f/(HH*WW));
}

// ---------------------------------------------------------------------------
// Kernel 2: MLP + softmax
// ---------------------------------------------------------------------------
__global__ void att_kernel(const float* __restrict__ w_fc1,
                           const float* __restrict__ w_fc2,
                           const float* __restrict__ b_fc2) {
    __shared__ float pooled_s[BB*CC];
    __shared__ float h_s[BB][HID];
    __shared__ float logits_s[BB][KK];
    int tid = threadIdx.x;
    for (int i = tid; i < BB*CC; i += blockDim.x) pooled_s[i] = g_pooled[i];
    __syncthreads();
    for (int t = tid; t < BB*HID; t += blockDim.x) {
        int b = t / HID, j = t - b*HID;
        float acc = 0.f;
        const float* wr = w_fc1 + j*CC;
        const float* pr = pooled_s + b*CC;
        #pragma unroll 4
        for (int c = 0; c < CC; c++) acc += pr[c]*wr[c];
        h_s[b][j] = fmaxf(acc, 0.f);
    }
    __syncthreads();
    if (tid < BB*KK) {
        int b = tid / KK, k = tid - b*KK;
        float acc = b_fc2[k];
        const float* wr = w_fc2 + k*HID;
        for (int j = 0; j < HID; j++) acc += h_s[b][j]*wr[j];
        logits_s[b][k] = acc * (1.0f/TEMP);
    }
    __syncthreads();
    if (tid < BB) {
        int b = tid;
        float m = logits_s[b][0];
        #pragma unroll
        for (int k = 1; k < KK; k++) m = fmaxf(m, logits_s[b][k]);
        float e[KK]; float s = 0.f;
        #pragma unroll
        for (int k = 0; k < KK; k++) { e[k] = expf(logits_s[b][k] - m); s += e[k]; }
        float inv = 1.0f / s;
        #pragma unroll
        for (int k = 0; k < KK; k++) g_att[b*KK + k] = e[k] * inv;
    }
}

// ---------------------------------------------------------------------------
// Kernel 3: aggregate weights -> bf16 hi/lo split, layout [b][tap][o][c]
// thread = (o,c); wt reads contiguous 36B per expert, writes coalesced in c.
// ---------------------------------------------------------------------------
__global__ void aggw_split_kernel(const float* __restrict__ wt) {
    int m = blockIdx.x*blockDim.x + threadIdx.x;     // o*CC + c
    if (m >= OO*CC) return;
    float w[KK][9];
    #pragma unroll
    for (int k = 0; k < KK; k++) {
        const float* src = wt + ((size_t)k*OO*CC + m)*9;
        #pragma unroll
        for (int t = 0; t < 9; t++) w[k][t] = src[t];
    }
    for (int b = 0; b < BB; b++) {
        float a0 = g_att[b*4+0], a1 = g_att[b*4+1];
        float a2 = g_att[b*4+2], a3 = g_att[b*4+3];
        #pragma unroll
        for (int t = 0; t < 9; t++) {
            float s = a0*w[0][t] + a1*w[1][t] + a2*w[2][t] + a3*w[3][t];
            __nv_bfloat16 hi = __float2bfloat16(s);
            float lo = s - __bfloat162float(hi);
            size_t off = ((size_t)(b*9 + t))*OO*CC + m;
            g_awhi[off] = hi;
            g_awlo[off] = __float2bfloat16(lo);
        }
    }
}

// ---------------------------------------------------------------------------
// Kernel 4: x -> transposed bf16 hi/lo split, layout [b][pixel][c]
// ---------------------------------------------------------------------------
__global__ void xsplit_kernel(const float* __restrict__ x) {
    __shared__ float t[32][33];
    int p0 = blockIdx.x*32, c0 = blockIdx.y*32, b = blockIdx.z;
    int tx = threadIdx.x, ty = threadIdx.y;
    #pragma unroll
    for (int k = 0; k < 4; k++) {
        int c = c0 + ty + k*8;
        t[ty + k*8][tx] = x[((size_t)(b*CC + c))*4096 + p0 + tx];
    }
    __syncthreads();
    #pragma unroll
    for (int k = 0; k < 4; k++) {
        int p = p0 + ty + k*8;
        float v = t[tx][ty + k*8];
        __nv_bfloat16 hi = __float2bfloat16(v);
        float lo = v - __bfloat162float(hi);
        size_t off = ((size_t)b*4096 + p)*CC + c0 + tx;
        g_xthi[off] = hi;
        g_xtlo[off] = __float2bfloat16(lo);
    }
}

// ---------------------------------------------------------------------------
// Kernel 5: conv as bf16-split implicit GEMM via mma.sync (legacy HMMA).
// CTA: 512 thr / 16 warps, tile M=128(o) x N=256(px); warp tile 32x64.
// K = 9 taps x 256 c = 72 chunks of 32; cp.async double-buffered pipeline.
// Per fragment set: hi*hi + hi*lo + lo*hi (3 MMAs) for fp32-grade accuracy.
// ---------------------------------------------------------------------------
#define N_TILE 256
#define ROW_B  80                         // 32 bf16 = 64B + 16B pad
#define A_VER  (128*ROW_B)                // 10240
#define B_OFF  (2*A_VER)                  // 20480
#define B_VER  (N_TILE*ROW_B)             // 20480
#define CHUNK_B (2*A_VER + 2*B_VER)       // 61440
#define CONV_DSMEM (2*CHUNK_B)            // 122880
#define NCHUNK 72

__device__ __forceinline__ void conv_issue(int i, uint32_t sbase, int tid,
                                           int b, int o0, int p0) {
    int tap = i >> 3;
    int c0  = (i & 7) << 5;
    int dy  = tap/3 - 1;
    int dx  = tap - (tap/3)*3 - 1;
    uint32_t base = sbase + (uint32_t)(i & 1)*CHUNK_B;
    // ---- A: [128 o][32 c] hi+lo ----
    {
        int row = tid >> 2, cv = tid & 3;
        size_t so = (((size_t)b*9 + tap)*OO + o0 + row)*CC + c0 + cv*8;
        uint32_t d = base + row*ROW_B + cv*16;
        cp16(d,         g_awhi + so, 16);
        cp16(d + A_VER, g_awlo + so, 16);
    }
    // ---- B: [256 n][32 c] hi+lo, tap-shifted with zfill ----
    #pragma unroll
    for (int k = 0; k < 2; k++) {
        int v  = tid + (k << 9);
        int n  = v >> 2, cv = v & 3;
        int p  = p0 + n;
        int y  = p >> 6, xx = p & 63;
        int sy = y + dy, sx = xx + dx;
        bool ok = ((unsigned)sy < 64u) && ((unsigned)sx < 64u);
        size_t so = ok ? (((size_t)(b*4096) + sy*64 + sx)*CC + c0 + cv*8) : 0;
        uint32_t sz = ok ? 16u : 0u;
        uint32_t d = base + B_OFF + n*ROW_B + cv*16;
        cp16(d,         g_xthi + so, sz);
        cp16(d + B_VER, g_xtlo + so, sz);
    }
}

__global__ __launch_bounds__(512, 1)
void conv_mma_kernel(const float* __restrict__ bias, float* __restrict__ out) {
    extern __shared__ char dsm[];
    const int tid = threadIdx.x;
    const int wid = tid >> 5;
    const int lid = tid & 31;
    const int pt  = blockIdx.x;
    const int oh  = blockIdx.y;
    const int b   = blockIdx.z;
    const int p0  = pt * N_TILE;
    const int o0  = oh * 128;
    const int wm  = wid & 3;            // m offset wm*32
    const int wn  = wid >> 2;           // n offset wn*64
    const uint32_t sbase = smem_u32(dsm);

    float acc[2][8][4];
    #pragma unroll
    for (int mt = 0; mt < 2; mt++)
        #pragma unroll
        for (int nt = 0; nt < 8; nt++)
            #pragma unroll
            for (int r = 0; r < 4; r++) acc[mt][nt][r] = 0.f;

    const uint32_t aAddr0 = (wm*32 + (lid & 15))*ROW_B + (lid >> 4)*16;
    const uint32_t bAddr0 = B_OFF + (wn*64 + (lid & 15))*ROW_B + (lid >> 4)*16;

    conv_issue(0, sbase, tid, b, o0, p0);
    asm volatile("cp.async.commit_group;" ::: "memory");

    for (int i = 0; i < NCHUNK; i++) {
        if (i < NCHUNK-1) {
            conv_issue(i+1, sbase, tid, b, o0, p0);
            asm volatile("cp.async.commit_group;" ::: "memory");
            asm volatile("cp.async.wait_group 1;" ::: "memory");
        } else {
            asm volatile("cp.async.wait_group 0;" ::: "memory");
        }
        __syncthreads();

        const uint32_t base = sbase + (uint32_t)(i & 1)*CHUNK_B;
        #pragma unroll
        for (int ks = 0; ks < 2; ks++) {
            uint32_t ah[2][4], al[2][4];
            #pragma unroll
            for (int mt = 0; mt < 2; mt++) {
                uint32_t a = base + aAddr0 + mt*16*ROW_B + ks*32;
                ldsm4(ah[mt], a);
                ldsm4(al[mt], a + A_VER);
            }
            #pragma unroll
            for (int np = 0; np < 4; np++) {
                uint32_t bh[4], bl[4];
                uint32_t ba = base + bAddr0 + np*16*ROW_B + ks*32;
                ldsm4(bh, ba);
                ldsm4(bl, ba + B_VER);
                #pragma unroll
                for (int mt = 0; mt < 2; mt++) {
                    #pragma unroll
                    for (int s = 0; s < 2; s++) {
                        float* d = acc[mt][np*2 + s];
                        mma_bf16(d, ah[mt], bh[s], bh[s+2]);
                        mma_bf16(d, ah[mt], bl[s], bl[s+2]);
                        mma_bf16(d, al[mt], bh[s], bh[s+2]);
                    }
                }
            }
        }
        __syncthreads();
    }

    // ---- epilogue: + agg_b, store float2 per mma D pair ----
    float a0 = g_att[b*4+0], a1 = g_att[b*4+1];
    float a2 = g_att[b*4+2], a3 = g_att[b*4+3];
    const int g = lid >> 2;
    const int tq = lid & 3;
    #pragma unroll
    for (int mt = 0; mt < 2; mt++) {
        int oA = o0 + wm*32 + mt*16 + g;
        int oB = oA + 8;
        float abA = a0*bias[oA] + a1*bias[OO+oA] + a2*bias[2*OO+oA] + a3*bias[3*OO+oA];
        float abB = a0*bias[oB] + a1*bias[OO+oB] + a2*bias[2*OO+oB] + a3*bias[3*OO+oB];
        float* opA = out + ((size_t)b*OO + oA)*4096 + p0;
        float* opB = out + ((size_t)b*OO + oB)*4096 + p0;
        #pragma unroll
        for (int nt = 0; nt < 8; nt++) {
            int n = wn*64 + nt*8 + 2*tq;
            *(float2*)(opA + n) = make_float2(acc[mt][nt][0] + abA,
                                              acc[mt][nt][1] + abA);
            *(float2*)(opB + n) = make_float2(acc[mt][nt][2] + abB,
                                              acc[mt][nt][3] + abB);
        }
    }
}

// ---------------------------------------------------------------------------
extern "C" void kernel_launch(void* const* d_in, const int* in_sizes, int n_in,
                              void* d_out, int out_size) {
    const float* x     = (const float*)d_in[0];
    const float* w_fc1 = (const float*)d_in[1];
    const float* w_fc2 = (const float*)d_in[2];
    const float* b_fc2 = (const float*)d_in[3];
    const float* wt    = (const float*)d_in[4];
    const float* bias  = (const float*)d_in[5];
    float* out = (float*)d_out;

    cudaFuncSetAttribute(conv_mma_kernel,
                         cudaFuncAttributeMaxDynamicSharedMemorySize,
                         CONV_DSMEM);

    pool_kernel<<<BB*CC, 128>>>(x);
    att_kernel<<<1, 1024>>>(w_fc1, w_fc2, b_fc2);
    aggw_split_kernel<<<(OO*CC + 255)/256, 256>>>(wt);
    xsplit_kernel<<<dim3(HH*WW/32, CC/32, BB), dim3(32, 8)>>>(x);
    conv_mma_kernel<<<dim3(16, 2, 16), 512, CONV_DSMEM>>>(bias, out);
}

// round 13
// speedup vs baseline: 2.5853x; 1.0933x over previous
#include <cuda_runtime.h>
#include <cuda_bf16.h>
#include <math.h>
#include <stdint.h>

#define BB 16
#define CC 256
#define HH 64
#define WW 64
#define KK 4
#define OO 256
#define HID 65
#define TEMP 34.0f

// ---------------------------------------------------------------------------
// device scratch
// ---------------------------------------------------------------------------
__device__ float g_pooled[BB*CC];
__device__ float g_att[BB*KK];
__device__ __nv_bfloat16 g_awhi[(size_t)BB*9*OO*CC];   // [b][tap][o][c]
__device__ __nv_bfloat16 g_awlo[(size_t)BB*9*OO*CC];
__device__ __nv_bfloat16 g_xthi[(size_t)BB*HH*WW*CC];  // [b][pixel][c]
__device__ __nv_bfloat16 g_xtlo[(size_t)BB*HH*WW*CC];

// ---------------------------------------------------------------------------
// PTX helpers (plain sm_80/90 features only -> valid on .target sm_103)
// ---------------------------------------------------------------------------
__device__ __forceinline__ uint32_t smem_u32(const void* p) {
    uint32_t a;
    asm("{ .reg .u64 t; cvta.to.shared.u64 t, %1; cvt.u32.u64 %0, t; }"
        : "=r"(a) : "l"(p));
    return a;
}
__device__ __forceinline__ void cp16(uint32_t dst, const void* src, uint32_t sz) {
    asm volatile("cp.async.cg.shared.global [%0], [%1], 16, %2;"
                 :: "r"(dst), "l"(src), "r"(sz) : "memory");
}
__device__ __forceinline__ void ldsm4(uint32_t* r, uint32_t addr) {
    asm volatile("ldmatrix.sync.aligned.m8n8.x4.shared.b16 {%0,%1,%2,%3}, [%4];"
                 : "=r"(r[0]), "=r"(r[1]), "=r"(r[2]), "=r"(r[3]) : "r"(addr));
}
__device__ __forceinline__ void mma_bf16(float* d, const uint32_t* a,
                                         uint32_t b0, uint32_t b1) {
    asm volatile(
        "mma.sync.aligned.m16n8k16.row.col.f32.bf16.bf16.f32 "
        "{%0,%1,%2,%3}, {%4,%5,%6,%7}, {%8,%9}, {%0,%1,%2,%3};"
        : "+f"(d[0]), "+f"(d[1]), "+f"(d[2]), "+f"(d[3])
        : "r"(a[0]), "r"(a[1]), "r"(a[2]), "r"(a[3]), "r"(b0), "r"(b1));
}

// ---------------------------------------------------------------------------
// Kernel 1: global average pool
// ---------------------------------------------------------------------------
__global__ void pool_kernel(const float* __restrict__ x) {
    int bc = blockIdx.x;
    const float4* p = (const float4*)(x + (size_t)bc * (HH*WW));
    float s = 0.f;
    for (int i = threadIdx.x; i < HH*WW/4; i += blockDim.x) {
        float4 v = p[i];
        s += (v.x + v.y) + (v.z + v.w);
    }
    __shared__ float red[128];
    red[threadIdx.x] = s;
    __syncthreads();
    for (int off = 64; off > 0; off >>= 1) {
        if (threadIdx.x < off) red[threadIdx.x] += red[threadIdx.x + off];
        __syncthreads();
    }
    if (threadIdx.x == 0) g_pooled[bc] = red[0] * (1.0f/(HH*WW));
}

// ---------------------------------------------------------------------------
// Kernel 2: MLP + softmax
// ---------------------------------------------------------------------------
__global__ void att_kernel(const float* __restrict__ w_fc1,
                           const float* __restrict__ w_fc2,
                           const float* __restrict__ b_fc2) {
    __shared__ float pooled_s[BB*CC];
    __shared__ float h_s[BB][HID];
    __shared__ float logits_s[BB][KK];
    int tid = threadIdx.x;
    for (int i = tid; i < BB*CC; i += blockDim.x) pooled_s[i] = g_pooled[i];
    __syncthreads();
    for (int t = tid; t < BB*HID; t += blockDim.x) {
        int b = t / HID, j = t - b*HID;
        float acc = 0.f;
        const float* wr = w_fc1 + j*CC;
        const float* pr = pooled_s + b*CC;
        #pragma unroll 4
        for (int c = 0; c < CC; c++) acc += pr[c]*wr[c];
        h_s[b][j] = fmaxf(acc, 0.f);
    }
    __syncthreads();
    if (tid < BB*KK) {
        int b = tid / KK, k = tid - b*KK;
        float acc = b_fc2[k];
        const float* wr = w_fc2 + k*HID;
        for (int j = 0; j < HID; j++) acc += h_s[b][j]*wr[j];
        logits_s[b][k] = acc * (1.0f/TEMP);
    }
    __syncthreads();
    if (tid < BB) {
        int b = tid;
        float m = logits_s[b][0];
        #pragma unroll
        for (int k = 1; k < KK; k++) m = fmaxf(m, logits_s[b][k]);
        float e[KK]; float s = 0.f;
        #pragma unroll
        for (int k = 0; k < KK; k++) { e[k] = expf(logits_s[b][k] - m); s += e[k]; }
        float inv = 1.0f / s;
        #pragma unroll
        for (int k = 0; k < KK; k++) g_att[b*KK + k] = e[k] * inv;
    }
}

// ---------------------------------------------------------------------------
// Kernel 3: aggregate weights -> bf16 hi/lo split, layout [b][tap][o][c]
// ---------------------------------------------------------------------------
__global__ void aggw_split_kernel(const float* __restrict__ wt) {
    int m = blockIdx.x*blockDim.x + threadIdx.x;     // o*CC + c
    if (m >= OO*CC) return;
    float w[KK][9];
    #pragma unroll
    for (int k = 0; k < KK; k++) {
        const float* src = wt + ((size_t)k*OO*CC + m)*9;
        #pragma unroll
        for (int t = 0; t < 9; t++) w[k][t] = src[t];
    }
    for (int b = 0; b < BB; b++) {
        float a0 = g_att[b*4+0], a1 = g_att[b*4+1];
        float a2 = g_att[b*4+2], a3 = g_att[b*4+3];
        #pragma unroll
        for (int t = 0; t < 9; t++) {
            float s = a0*w[0][t] + a1*w[1][t] + a2*w[2][t] + a3*w[3][t];
            __nv_bfloat16 hi = __float2bfloat16(s);
            float lo = s - __bfloat162float(hi);
            size_t off = ((size_t)(b*9 + t))*OO*CC + m;
            g_awhi[off] = hi;
            g_awlo[off] = __float2bfloat16(lo);
        }
    }
}

// ---------------------------------------------------------------------------
// Kernel 4: x -> transposed bf16 hi/lo split, layout [b][pixel][c]
// ---------------------------------------------------------------------------
__global__ void xsplit_kernel(const float* __restrict__ x) {
    __shared__ float t[32][33];
    int p0 = blockIdx.x*32, c0 = blockIdx.y*32, b = blockIdx.z;
    int tx = threadIdx.x, ty = threadIdx.y;
    #pragma unroll
    for (int k = 0; k < 4; k++) {
        int c = c0 + ty + k*8;
        t[ty + k*8][tx] = x[((size_t)(b*CC + c))*4096 + p0 + tx];
    }
    __syncthreads();
    #pragma unroll
    for (int k = 0; k < 4; k++) {
        int p = p0 + ty + k*8;
        float v = t[tx][ty + k*8];
        __nv_bfloat16 hi = __float2bfloat16(v);
        float lo = v - __bfloat162float(hi);
        size_t off = ((size_t)b*4096 + p)*CC + c0 + tx;
        g_xthi[off] = hi;
        g_xtlo[off] = __float2bfloat16(lo);
    }
}

// ---------------------------------------------------------------------------
// Kernel 5: conv as bf16-split implicit GEMM with 2-D halo tap reuse.
// CTA: 512 thr / 16 warps, tile M=128(o) x N=256(px = 16x16 spatial).
// B = 18x18 halo tile [324 rows][32 c] loaded ONCE per c-chunk, reused by all
// 9 taps via constant smem row offset. A loaded per (chunk, tap).
// Row layout: [32c hi (64B)][32c lo (64B)][16B pad], ROW_B=144.
// 3 MMAs per fragment pair: hi*hi + hi*lo + lo*hi.
// ---------------------------------------------------------------------------
#define ROW_B  144
#define B_ROWS 324                         // 18*18
#define ABUF   (128*ROW_B)                 // 18432
#define BBUF   (B_ROWS*ROW_B)              // 46656
#define CONV_DSMEM (2*ABUF + 2*BBUF)       // 130176

__device__ __forceinline__ void issueA(uint32_t dst, int b, int tap, int o0,
                                       int c0, int tid) {
    #pragma unroll
    for (int j = 0; j < 2; j++) {
        int v   = tid*2 + j;               // 0..1023
        int row = v >> 3;
        int p   = v & 7;
        size_t src = (((size_t)b*9 + tap)*OO + o0 + row)*CC + c0 + (p & 3)*8;
        uint32_t d = dst + row*ROW_B + (p & 3)*16 + (p >> 2)*64;
        cp16(d, (p < 4 ? g_awhi : g_awlo) + src, 16);
    }
}

__device__ __forceinline__ void issueB(uint32_t dst, int b, int y0, int x0,
                                       int c0, int tid) {
    #pragma unroll
    for (int k = 0; k < 6; k++) {
        int v = tid + k*512;
        if (v < B_ROWS*8) {
            int row = v >> 3;
            int p   = v & 7;
            int hy  = row / 18;
            int hx  = row - hy*18;
            int gy  = y0 - 1 + hy;
            int gx  = x0 - 1 + hx;
            bool ok = ((unsigned)gy < 64u) && ((unsigned)gx < 64u);
            size_t src = ok ? ((size_t)(b*4096 + gy*64 + gx)*CC + c0 + (p & 3)*8)
                            : 0;
            uint32_t sz = ok ? 16u : 0u;
            uint32_t d = dst + row*ROW_B + (p & 3)*16 + (p >> 2)*64;
            cp16(d, (p < 4 ? g_xthi : g_xtlo) + src, sz);
        }
    }
}

__global__ __launch_bounds__(512, 1)
void conv_mma_kernel(const float* __restrict__ bias, float* __restrict__ out) {
    extern __shared__ char dsm[];
    const int tid = threadIdx.x;
    const int wid = tid >> 5;
    const int lid = tid & 31;
    const int pt  = blockIdx.x;            // 0..15: 4x4 tiles of 16x16 px
    const int oh  = blockIdx.y;
    const int b   = blockIdx.z;
    const int y0  = (pt >> 2) * 16;
    const int x0  = (pt & 3)  * 16;
    const int o0  = oh * 128;
    const int wm  = wid & 3;               // m offset wm*32
    const int wn  = wid >> 2;              // n offset wn*64
    const int l15 = lid & 15;
    const int l16 = lid >> 4;

    const uint32_t sbase = smem_u32(dsm);
    const uint32_t aB0 = sbase;
    const uint32_t aB1 = sbase + ABUF;
    const uint32_t bB0 = sbase + 2*ABUF;
    const uint32_t bB1 = sbase + 2*ABUF + BBUF;

    float acc[2][8][4];
    #pragma unroll
    for (int mt = 0; mt < 2; mt++)
        #pragma unroll
        for (int nt = 0; nt < 8; nt++)
            #pragma unroll
            for (int r = 0; r < 4; r++) acc[mt][nt][r] = 0.f;

    // lane-invariant fragment address components
    const uint32_t aLane = (wm*32 + l15)*ROW_B + l16*16;
    // B halo: n = wn*64 + np*16 + l15 -> smem row = (wn*4+np+1)*18 + l15+1
    const uint32_t bLane = ((wn*4 + 1)*18 + l15 + 1)*ROW_B + l16*16;

    issueB(bB0, b, y0, x0, 0, tid);
    issueA(aB0, b, 0, o0, 0, tid);
    asm volatile("cp.async.commit_group;" ::: "memory");

    int chunk = 0, tap = 0;
    for (int it = 0; it < 72; it++) {
        // prefetch next iteration
        if (it < 71) {
            int ntap = tap + 1, nchunk = chunk;
            if (ntap == 9) { ntap = 0; nchunk++; }
            issueA((it + 1) & 1 ? aB1 : aB0, b, ntap, o0, nchunk*32, tid);
            if (ntap == 0)
                issueB(nchunk & 1 ? bB1 : bB0, b, y0, x0, nchunk*32, tid);
            asm volatile("cp.async.commit_group;" ::: "memory");
            asm volatile("cp.async.wait_group 1;" ::: "memory");
        } else {
            asm volatile("cp.async.wait_group 0;" ::: "memory");
        }
        __syncthreads();

        const int dy = tap/3 - 1;
        const int dx = tap - (tap/3)*3 - 1;
        const uint32_t aa = ((it & 1) ? aB1 : aB0) + aLane;
        const uint32_t bb = ((chunk & 1) ? bB1 : bB0) + bLane
                          + (uint32_t)((dy*18 + dx) * ROW_B);

        #pragma unroll
        for (int ks = 0; ks < 2; ks++) {
            uint32_t ah[2][4], al[2][4];
            #pragma unroll
            for (int mt = 0; mt < 2; mt++) {
                uint32_t a = aa + mt*16*ROW_B + ks*32;
                ldsm4(ah[mt], a);
                ldsm4(al[mt], a + 64);
            }
            #pragma unroll
            for (int np = 0; np < 4; np++) {
                uint32_t bh[4], bl[4];
                uint32_t ba = bb + np*(18*ROW_B) + ks*32;
                ldsm4(bh, ba);
                ldsm4(bl, ba + 64);
                #pragma unroll
                for (int mt = 0; mt < 2; mt++) {
                    #pragma unroll
                    for (int s = 0; s < 2; s++) {
                        float* d = acc[mt][np*2 + s];
                        mma_bf16(d, ah[mt], bh[s], bh[s+2]);
                        mma_bf16(d, ah[mt], bl[s], bl[s+2]);
                        mma_bf16(d, al[mt], bh[s], bh[s+2]);
                    }
                }
            }
        }
        __syncthreads();

        if (++tap == 9) { tap = 0; chunk++; }
    }

    // ---- epilogue: + agg_b, store float2; n -> (yy,xx) within 16x16 tile ----
    float a0 = g_att[b*4+0], a1 = g_att[b*4+1];
    float a2 = g_att[b*4+2], a3 = g_att[b*4+3];
    const int g  = lid >> 2;
    const int tq = lid & 3;
    #pragma unroll
    for (int mt = 0; mt < 2; mt++) {
        int oA = o0 + wm*32 + mt*16 + g;
        int oB = oA + 8;
        float abA = a0*bias[oA] + a1*bias[OO+oA] + a2*bias[2*OO+oA] + a3*bias[3*OO+oA];
        float abB = a0*bias[oB] + a1*bias[OO+oB] + a2*bias[2*OO+oB] + a3*bias[3*OO+oB];
        float* opA = out + ((size_t)b*OO + oA)*4096;
        float* opB = out + ((size_t)b*OO + oB)*4096;
        #pragma unroll
        for (int nt = 0; nt < 8; nt++) {
            int n  = wn*64 + nt*8 + 2*tq;
            int yy = n >> 4;
            int xx = n & 15;
            int off = (y0 + yy)*64 + x0 + xx;
            *(float2*)(opA + off) = make_float2(acc[mt][nt][0] + abA,
                                                acc[mt][nt][1] + abA);
            *(float2*)(opB + off) = make_float2(acc[mt][nt][2] + abB,
                                                acc[mt][nt][3] + abB);
        }
    }
}

// ---------------------------------------------------------------------------
extern "C" void kernel_launch(void* const* d_in, const int* in_sizes, int n_in,
                              void* d_out, int out_size) {
    const float* x     = (const float*)d_in[0];
    const float* w_fc1 = (const float*)d_in[1];
    const float* w_fc2 = (const float*)d_in[2];
    const float* b_fc2 = (const float*)d_in[3];
    const float* wt    = (const float*)d_in[4];
    const float* bias  = (const float*)d_in[5];
    float* out = (float*)d_out;

    cudaFuncSetAttribute(conv_mma_kernel,
                         cudaFuncAttributeMaxDynamicSharedMemorySize,
                         CONV_DSMEM);

    pool_kernel<<<BB*CC, 128>>>(x);
    att_kernel<<<1, 1024>>>(w_fc1, w_fc2, b_fc2);
    aggw_split_kernel<<<(OO*CC + 255)/256, 256>>>(wt);
    xsplit_kernel<<<dim3(HH*WW/32, CC/32, BB), dim3(32, 8)>>>(x);
    conv_mma_kernel<<<dim3(16, 2, 16), 512, CONV_DSMEM>>>(bias, out);
}

// round 17
// speedup vs baseline: 3.6923x; 1.4282x over previous
#include <cuda_runtime.h>
#include <cuda_fp16.h>
#include <math.h>
#include <stdint.h>

#define BB 16
#define CC 256
#define HH 64
#define WW 64
#define KK 4
#define OO 256
#define HID 65
#define TEMP 34.0f

// ---------------------------------------------------------------------------
// device scratch
// ---------------------------------------------------------------------------
__device__ float g_pooled[BB*CC];
__device__ float g_att[BB*KK];
__device__ __half g_aw[(size_t)BB*9*OO*CC];      // [b][tap][o][c]  fp16(w)
__device__ __half g_xthi[(size_t)BB*HH*WW*CC];   // [b][pixel][c]   fp16 hi
__device__ __half g_xtlo[(size_t)BB*HH*WW*CC];   // [b][pixel][c]   fp16 lo

// ---------------------------------------------------------------------------
// PTX helpers (plain sm_80/90 features only -> valid on .target sm_103)
// ---------------------------------------------------------------------------
__device__ __forceinline__ uint32_t smem_u32(const void* p) {
    uint32_t a;
    asm("{ .reg .u64 t; cvta.to.shared.u64 t, %1; cvt.u32.u64 %0, t; }"
        : "=r"(a) : "l"(p));
    return a;
}
__device__ __forceinline__ void cp16(uint32_t dst, const void* src, uint32_t sz) {
    asm volatile("cp.async.cg.shared.global [%0], [%1], 16, %2;"
                 :: "r"(dst), "l"(src), "r"(sz) : "memory");
}
__device__ __forceinline__ void ldsm4(uint32_t* r, uint32_t addr) {
    asm volatile("ldmatrix.sync.aligned.m8n8.x4.shared.b16 {%0,%1,%2,%3}, [%4];"
                 : "=r"(r[0]), "=r"(r[1]), "=r"(r[2]), "=r"(r[3]) : "r"(addr));
}
__device__ __forceinline__ void mma_f16(float* d, const uint32_t* a,
                                        uint32_t b0, uint32_t b1) {
    asm volatile(
        "mma.sync.aligned.m16n8k16.row.col.f32.f16.f16.f32 "
        "{%0,%1,%2,%3}, {%4,%5,%6,%7}, {%8,%9}, {%0,%1,%2,%3};"
        : "+f"(d[0]), "+f"(d[1]), "+f"(d[2]), "+f"(d[3])
        : "r"(a[0]), "r"(a[1]), "r"(a[2]), "r"(a[3]), "r"(b0), "r"(b1));
}

// ---------------------------------------------------------------------------
// Kernel 1: global average pool
// ---------------------------------------------------------------------------
__global__ void pool_kernel(const float* __restrict__ x) {
    int bc = blockIdx.x;
    const float4* p = (const float4*)(x + (size_t)bc * (HH*WW));
    float s = 0.f;
    for (int i = threadIdx.x; i < HH*WW/4; i += blockDim.x) {
        float4 v = p[i];
        s += (v.x + v.y) + (v.z + v.w);
    }
    __shared__ float red[128];
    red[threadIdx.x] = s;
    __syncthreads();
    for (int off = 64; off > 0; off >>= 1) {
        if (threadIdx.x < off) red[threadIdx.x] += red[threadIdx.x + off];
        __syncthreads();
    }
    if (threadIdx.x == 0) g_pooled[bc] = red[0] * (1.0f/(HH*WW));
}

// ---------------------------------------------------------------------------
// Kernel 2: MLP + softmax
// ---------------------------------------------------------------------------
__global__ void att_kernel(const float* __restrict__ w_fc1,
                           const float* __restrict__ w_fc2,
                           const float* __restrict__ b_fc2) {
    __shared__ float pooled_s[BB*CC];
    __shared__ float h_s[BB][HID];
    __shared__ float logits_s[BB][KK];
    int tid = threadIdx.x;
    for (int i = tid; i < BB*CC; i += blockDim.x) pooled_s[i] = g_pooled[i];
    __syncthreads();
    for (int t = tid; t < BB*HID; t += blockDim.x) {
        int b = t / HID, j = t - b*HID;
        float acc = 0.f;
        const float* wr = w_fc1 + j*CC;
        const float* pr = pooled_s + b*CC;
        #pragma unroll 4
        for (int c = 0; c < CC; c++) acc += pr[c]*wr[c];
        h_s[b][j] = fmaxf(acc, 0.f);
    }
    __syncthreads();
    if (tid < BB*KK) {
        int b = tid / KK, k = tid - b*KK;
        float acc = b_fc2[k];
        const float* wr = w_fc2 + k*HID;
        for (int j = 0; j < HID; j++) acc += h_s[b][j]*wr[j];
        logits_s[b][k] = acc * (1.0f/TEMP);
    }
    __syncthreads();
    if (tid < BB) {
        int b = tid;
        float m = logits_s[b][0];
        #pragma unroll
        for (int k = 1; k < KK; k++) m = fmaxf(m, logits_s[b][k]);
        float e[KK]; float s = 0.f;
        #pragma unroll
        for (int k = 0; k < KK; k++) { e[k] = expf(logits_s[b][k] - m); s += e[k]; }
        float inv = 1.0f / s;
        #pragma unroll
        for (int k = 0; k < KK; k++) g_att[b*KK + k] = e[k] * inv;
    }
}

// ---------------------------------------------------------------------------
// Kernel 3: aggregate weights -> fp16, layout [b][tap][o][c]
// ---------------------------------------------------------------------------
__global__ void aggw_split_kernel(const float* __restrict__ wt) {
    int m = blockIdx.x*blockDim.x + threadIdx.x;     // o*CC + c
    if (m >= OO*CC) return;
    float w[KK][9];
    #pragma unroll
    for (int k = 0; k < KK; k++) {
        const float* src = wt + ((size_t)k*OO*CC + m)*9;
        #pragma unroll
        for (int t = 0; t < 9; t++) w[k][t] = src[t];
    }
    for (int b = 0; b < BB; b++) {
        float a0 = g_att[b*4+0], a1 = g_att[b*4+1];
        float a2 = g_att[b*4+2], a3 = g_att[b*4+3];
        #pragma unroll
        for (int t = 0; t < 9; t++) {
            float s = a0*w[0][t] + a1*w[1][t] + a2*w[2][t] + a3*w[3][t];
            g_aw[((size_t)(b*9 + t))*OO*CC + m] = __float2half(s);
        }
    }
}

// ---------------------------------------------------------------------------
// Kernel 4: x -> transposed fp16 hi/lo split, layout [b][pixel][c]
// ---------------------------------------------------------------------------
__global__ void xsplit_kernel(const float* __restrict__ x) {
    __shared__ float t[32][33];
    int p0 = blockIdx.x*32, c0 = blockIdx.y*32, b = blockIdx.z;
    int tx = threadIdx.x, ty = threadIdx.y;
    #pragma unroll
    for (int k = 0; k < 4; k++) {
        int c = c0 + ty + k*8;
        t[ty + k*8][tx] = x[((size_t)(b*CC + c))*4096 + p0 + tx];
    }
    __syncthreads();
    #pragma unroll
    for (int k = 0; k < 4; k++) {
        int p = p0 + ty + k*8;
        float v = t[tx][ty + k*8];
        __half hi = __float2half(v);
        float lo = v - __half2float(hi);
        size_t off = ((size_t)b*4096 + p)*CC + c0 + tx;
        g_xthi[off] = hi;
        g_xtlo[off] = __float2half(lo);
    }
}

// ---------------------------------------------------------------------------
// Kernel 5: conv as fp16 2-term-split implicit GEMM with 2-D halo tap reuse.
// CTA: 512 thr / 16 warps, tile M=128(o) x N=256(px = 16x16 spatial).
// B = 18x18 halo tile [324 rows][32c hi | 32c lo | pad] per c-chunk; all 9 taps
// reuse it via constant smem row offset. A (fp16 w, hi only) per (chunk, tap).
// 2 MMAs per fragment pair: w*x_hi + w*x_lo.
// ---------------------------------------------------------------------------
#define ROW_A  80                          // 32c fp16 = 64B + 16B pad
#define ROW_B  144                         // 64B hi + 64B lo + 16B pad
#define B_ROWS 324                         // 18*18
#define ABUF   (128*ROW_A)                 // 10240
#define BBUF   (B_ROWS*ROW_B)              // 46656
#define CONV_DSMEM (2*ABUF + 2*BBUF)       // 113792

__device__ __forceinline__ void issueA(uint32_t dst, int b, int tap, int o0,
                                       int c0, int tid) {
    int row = tid >> 2;                    // 0..127
    int p   = tid & 3;
    size_t src = (((size_t)b*9 + tap)*OO + o0 + row)*CC + c0 + p*8;
    cp16(dst + row*ROW_A + p*16, g_aw + src, 16);
}

__device__ __forceinline__ void issueB(uint32_t dst, int b, int y0, int x0,
                                       int c0, int tid) {
    #pragma unroll
    for (int k = 0; k < 6; k++) {
        int v = tid + k*512;
        if (v < B_ROWS*8) {
            int row = v >> 3;
            int p   = v & 7;
            int hy  = row / 18;
            int hx  = row - hy*18;
            int gy  = y0 - 1 + hy;
            int gx  = x0 - 1 + hx;
            bool ok = ((unsigned)gy < 64u) && ((unsigned)gx < 64u);
            size_t src = ok ? ((size_t)(b*4096 + gy*64 + gx)*CC + c0 + (p & 3)*8)
                            : 0;
            uint32_t sz = ok ? 16u : 0u;
            uint32_t d = dst + row*ROW_B + (p & 3)*16 + (p >> 2)*64;
            cp16(d, (p < 4 ? g_xthi : g_xtlo) + src, sz);
        }
    }
}

__global__ __launch_bounds__(512, 1)
void conv_mma_kernel(const float* __restrict__ bias, float* __restrict__ out) {
    extern __shared__ char dsm[];
    const int tid = threadIdx.x;
    const int wid = tid >> 5;
    const int lid = tid & 31;
    const int pt  = blockIdx.x;            // 0..15: 4x4 tiles of 16x16 px
    const int oh  = blockIdx.y;
    const int b   = blockIdx.z;
    const int y0  = (pt >> 2) * 16;
    const int x0  = (pt & 3)  * 16;
    const int o0  = oh * 128;
    const int wm  = wid & 3;               // m offset wm*32
    const int wn  = wid >> 2;              // n offset wn*64
    const int l15 = lid & 15;
    const int l16 = lid >> 4;

    const uint32_t sbase = smem_u32(dsm);
    const uint32_t aB0 = sbase;
    const uint32_t aB1 = sbase + ABUF;
    const uint32_t bB0 = sbase + 2*ABUF;
    const uint32_t bB1 = sbase + 2*ABUF + BBUF;

    float acc[2][8][4];
    #pragma unroll
    for (int mt = 0; mt < 2; mt++)
        #pragma unroll
        for (int nt = 0; nt < 8; nt++)
            #pragma unroll
            for (int r = 0; r < 4; r++) acc[mt][nt][r] = 0.f;

    const uint32_t aLane = (wm*32 + l15)*ROW_A + l16*16;
    // B halo: n = wn*64 + np*16 + l15 -> smem row = (wn*4+np+1)*18 + l15+1
    const uint32_t bLane = ((wn*4 + 1)*18 + l15 + 1)*ROW_B + l16*16;

    issueB(bB0, b, y0, x0, 0, tid);
    issueA(aB0, b, 0, o0, 0, tid);
    asm volatile("cp.async.commit_group;" ::: "memory");

    int chunk = 0, tap = 0;
    for (int it = 0; it < 72; it++) {
        if (it < 71) {
            int ntap = tap + 1, nchunk = chunk;
            if (ntap == 9) { ntap = 0; nchunk++; }
            issueA((it + 1) & 1 ? aB1 : aB0, b, ntap, o0, nchunk*32, tid);
            if (ntap == 0)
                issueB(nchunk & 1 ? bB1 : bB0, b, y0, x0, nchunk*32, tid);
            asm volatile("cp.async.commit_group;" ::: "memory");
            asm volatile("cp.async.wait_group 1;" ::: "memory");
        } else {
            asm volatile("cp.async.wait_group 0;" ::: "memory");
        }
        __syncthreads();

        const int dy = tap/3 - 1;
        const int dx = tap - (tap/3)*3 - 1;
        const uint32_t aa = ((it & 1) ? aB1 : aB0) + aLane;
        const uint32_t bb = ((chunk & 1) ? bB1 : bB0) + bLane
                          + (uint32_t)((dy*18 + dx) * ROW_B);

        #pragma unroll
        for (int ks = 0; ks < 2; ks++) {
            uint32_t ah[2][4];
            #pragma unroll
            for (int mt = 0; mt < 2; mt++)
                ldsm4(ah[mt], aa + mt*16*ROW_A + ks*32);
            #pragma unroll
            for (int np = 0; np < 4; np++) {
                uint32_t bh[4], bl[4];
                uint32_t ba = bb + np*(18*ROW_B) + ks*32;
                ldsm4(bh, ba);
                ldsm4(bl, ba + 64);
                #pragma unroll
                for (int mt = 0; mt < 2; mt++) {
                    #pragma unroll
                    for (int s = 0; s < 2; s++) {
                        float* d = acc[mt][np*2 + s];
                        mma_f16(d, ah[mt], bh[s], bh[s+2]);
                        mma_f16(d, ah[mt], bl[s], bl[s+2]);
                    }
                }
            }
        }
        __syncthreads();

        if (++tap == 9) { tap = 0; chunk++; }
    }

    // ---- epilogue: + agg_b, store float2; n -> (yy,xx) within 16x16 tile ----
    float a0 = g_att[b*4+0], a1 = g_att[b*4+1];
    float a2 = g_att[b*4+2], a3 = g_att[b*4+3];
    const int g  = lid >> 2;
    const int tq = lid & 3;
    #pragma unroll
    for (int mt = 0; mt < 2; mt++) {
        int oA = o0 + wm*32 + mt*16 + g;
        int oB = oA + 8;
        float abA = a0*bias[oA] + a1*bias[OO+oA] + a2*bias[2*OO+oA] + a3*bias[3*OO+oA];
        float abB = a0*bias[oB] + a1*bias[OO+oB] + a2*bias[2*OO+oB] + a3*bias[3*OO+oB];
        float* opA = out + ((size_t)b*OO + oA)*4096;
        float* opB = out + ((size_t)b*OO + oB)*4096;
        #pragma unroll
        for (int nt = 0; nt < 8; nt++) {
            int n  = wn*64 + nt*8 + 2*tq;
            int yy = n >> 4;
            int xx = n & 15;
            int off = (y0 + yy)*64 + x0 + xx;
            *(float2*)(opA + off) = make_float2(acc[mt][nt][0] + abA,
                                                acc[mt][nt][1] + abA);
            *(float2*)(opB + off) = make_float2(acc[mt][nt][2] + abB,
                                                acc[mt][nt][3] + abB);
        }
    }
}

// ---------------------------------------------------------------------------
extern "C" void kernel_launch(void* const* d_in, const int* in_sizes, int n_in,
                              void* d_out, int out_size) {
    const float* x     = (const float*)d_in[0];
    const float* w_fc1 = (const float*)d_in[1];
    const float* w_fc2 = (const float*)d_in[2];
    const float* b_fc2 = (const float*)d_in[3];
    const float* wt    = (const float*)d_in[4];
    const float* bias  = (const float*)d_in[5];
    float* out = (float*)d_out;

    cudaFuncSetAttribute(conv_mma_kernel,
                         cudaFuncAttributeMaxDynamicSharedMemorySize,
                         CONV_DSMEM);

    pool_kernel<<<BB*CC, 128>>>(x);
    att_kernel<<<1, 1024>>>(w_fc1, w_fc2, b_fc2);
    aggw_split_kernel<<<(OO*CC + 255)/256, 256>>>(wt);
    xsplit_kernel<<<dim3(HH*WW/32, CC/32, BB), dim3(32, 8)>>>(x);
    conv_mma_kernel<<<dim3(16, 2, 16), 512, CONV_DSMEM>>>(bias, out);
}